// round 13
// baseline (speedup 1.0000x reference)
#include <cuda_runtime.h>
#include <cuda_fp16.h>
#include <cstdint>
#include <cstddef>

#define DEVINL __device__ __forceinline__

static constexpr int Bn = 8, En = 2048, Nn = 2048, Fn = 128;

// Scratch (__device__ globals; allocations are forbidden)
__device__ __half g_embHT[(size_t)Bn * Fn * Nn];   // [b][f][n] fp16, 4 MB
__device__ __half g_WH[Fn * Fn];                   // W fp16 [f_out][f_in]

// ---------------------------------------------------------------- helpers

DEVINL uint32_t smem_u32(const void* p) {
    uint32_t a;
    asm("{ .reg .u64 t; cvta.to.shared.u64 t, %1; cvt.u32.u64 %0, t; }"
        : "=r"(a) : "l"(p));
    return a;
}

DEVINL void ldsm_x4(uint32_t* r, uint32_t addr) {
    asm volatile("ldmatrix.sync.aligned.m8n8.x4.shared.b16 {%0,%1,%2,%3}, [%4];"
                 : "=r"(r[0]), "=r"(r[1]), "=r"(r[2]), "=r"(r[3]) : "r"(addr));
}

DEVINL void mma_16816(float* d, const uint32_t* a, const uint32_t* b) {
    asm volatile(
        "mma.sync.aligned.m16n8k16.row.col.f32.f16.f16.f32 "
        "{%0,%1,%2,%3}, {%4,%5,%6,%7}, {%8,%9}, {%0,%1,%2,%3};"
        : "+f"(d[0]), "+f"(d[1]), "+f"(d[2]), "+f"(d[3])
        : "r"(a[0]), "r"(a[1]), "r"(a[2]), "r"(a[3]), "r"(b[0]), "r"(b[1]));
}

DEVINL void cp_async16(uint32_t dst, const void* src) {
    asm volatile("cp.async.cg.shared.global [%0], [%1], 16;"
                 :: "r"(dst), "l"(src) : "memory");
}
#define CP_COMMIT()  asm volatile("cp.async.commit_group;" ::: "memory")
#define CP_WAIT(N)   asm volatile("cp.async.wait_group %0;" :: "n"(N) : "memory")

// ---------------------------------------------------------------- prelude kernels

// emb [b][n][f] fp32 -> g_embHT [b][f][n] fp16
__global__ void ktr_kernel(const float* __restrict__ emb) {
    __shared__ float t[32][33];
    const int b = blockIdx.z, n0 = blockIdx.x * 32, f0 = blockIdx.y * 32;
    const int x = threadIdx.x, y = threadIdx.y;
#pragma unroll
    for (int yy = y; yy < 32; yy += 8)
        t[yy][x] = emb[((size_t)b * Nn + n0 + yy) * Fn + f0 + x];
    __syncthreads();
#pragma unroll
    for (int yy = y; yy < 32; yy += 8)
        g_embHT[((size_t)b * Fn + f0 + yy) * Nn + n0 + x] = __float2half(t[x][yy]);
}

__global__ void kwc_kernel(const float* __restrict__ W) {
    const int i = blockIdx.x * 256 + threadIdx.x;
    g_WH[i] = __float2half(W[i]);
}

// ---------------------------------------------------------------- fused main kernel
// CTA tile: M=128 hyperedges, N=F=128, K=2048 vertices, BK=64, 2-stage pipeline.
// GEMM1 (mask @ embT, fp16 HMMA, f32 acc) -> /norm -> fp16 P (smem)
// GEMM2 (P @ W^T) -> +bias, relu -> out.

static constexpr int SA_STRIDE = 144;   // 64 halves + 8 pad  (36 words -> 4r mod 32)
static constexpr int SW_STRIDE = 272;   // 128 halves + 8 pad (68 words -> 4r mod 32)
static constexpr int A_BUF   = 128 * SA_STRIDE;          // 18432
static constexpr int OFF_A   = 0;                        // double buffer, P reuses
static constexpr int OFF_B   = 2 * A_BUF;                // 36864, double buffer
static constexpr int OFF_W   = OFF_B + 2 * A_BUF;        // 73728
static constexpr int OFF_NORM = OFF_W + 128 * SW_STRIDE; // 108544
static constexpr int OFF_BIAS = OFF_NORM + 512;          // 109056
static constexpr int SMEM_TOT = OFF_BIAS + 512;          // 109568

__global__ void __launch_bounds__(256, 1)
kmain(const float* __restrict__ adj, const float* __restrict__ bias,
      float* __restrict__ out) {
    extern __shared__ char sm[];
    const uint32_t sb = smem_u32(sm);
    const int tid = threadIdx.x;
    const int lane = tid & 31, wid = tid >> 5;
    const int b  = blockIdx.x >> 4;
    const int e0 = (blockIdx.x & 15) << 7;

    float* sbias = (float*)(sm + OFF_BIAS);
    int*   snorm = (int*)(sm + OFF_NORM);
    if (tid < 128) sbias[tid] = bias[tid];

    // --- prologue: cp.async W tile (32 KB fp16) into sW
#pragma unroll
    for (int it = 0; it < 8; it++) {
        const int row = it * 16 + (tid >> 4), c = tid & 15;
        cp_async16(sb + OFF_W + row * SW_STRIDE + c * 16, g_WH + row * Fn + c * 8);
    }

    const __half* embB = g_embHT + (size_t)b * Fn * Nn;
    auto issueB = [&](int kc, int p) {
#pragma unroll
        for (int s = 0; s < 4; s++) {
            const int f = s * 32 + (tid >> 3), c = tid & 7;
            cp_async16(sb + OFF_B + p * A_BUF + f * SA_STRIDE + c * 16,
                       embB + (size_t)f * Nn + kc * 64 + c * 8);
        }
    };

    const float* adjB = adj + ((size_t)b * En + e0) * Nn;
    float4 av[4][2];
    auto ldgA = [&](int kc) {
#pragma unroll
        for (int s = 0; s < 4; s++) {
            const float* p = adjB + (size_t)(s * 32 + (tid >> 3)) * Nn
                           + kc * 64 + (tid & 7) * 8;
            av[s][0] = *(const float4*)p;
            av[s][1] = *(const float4*)(p + 4);
        }
    };

    int cnt[4] = {0, 0, 0, 0};
    auto stsA = [&](int p) {
#pragma unroll
        for (int s = 0; s < 4; s++) {
            const int row = s * 32 + (tid >> 3);
            uint32_t m0 = (av[s][0].x == -1.0f) ? 0x3C00u : 0u;
            uint32_t m1 = (av[s][0].y == -1.0f) ? 0x3C00u : 0u;
            uint32_t m2 = (av[s][0].z == -1.0f) ? 0x3C00u : 0u;
            uint32_t m3 = (av[s][0].w == -1.0f) ? 0x3C00u : 0u;
            uint32_t m4 = (av[s][1].x == -1.0f) ? 0x3C00u : 0u;
            uint32_t m5 = (av[s][1].y == -1.0f) ? 0x3C00u : 0u;
            uint32_t m6 = (av[s][1].z == -1.0f) ? 0x3C00u : 0u;
            uint32_t m7 = (av[s][1].w == -1.0f) ? 0x3C00u : 0u;
            cnt[s] += (m0 ? 1 : 0) + (m1 ? 1 : 0) + (m2 ? 1 : 0) + (m3 ? 1 : 0)
                    + (m4 ? 1 : 0) + (m5 ? 1 : 0) + (m6 ? 1 : 0) + (m7 ? 1 : 0);
            uint4 q;
            q.x = m0 | (m1 << 16); q.y = m2 | (m3 << 16);
            q.z = m4 | (m5 << 16); q.w = m6 | (m7 << 16);
            *(uint4*)(sm + OFF_A + p * A_BUF + row * SA_STRIDE + (tid & 7) * 16) = q;
        }
    };

    issueB(0, 0);
    CP_COMMIT();                // G0 = W + B0
    ldgA(0);
    issueB(1, 1);
    CP_COMMIT();                // G1 = B1
    stsA(0);
    CP_WAIT(1);                 // G0 complete
    __syncthreads();

    // --- warp tiling: 4 (M) x 2 (N); warp tile 32m x 64n
    const int mw = wid & 3, nw = wid >> 2;
    const int m0 = mw * 32, n0 = nw * 64;
    const int lr = lane & 15, lc = lane >> 4;
    const int gid = lane >> 2, tig = lane & 3;

    float d[2][8][4];
#pragma unroll
    for (int i = 0; i < 2; i++)
#pragma unroll
        for (int j = 0; j < 8; j++)
#pragma unroll
            for (int k = 0; k < 4; k++) d[i][j][k] = 0.0f;

    for (int kc = 0; kc < 32; kc++) {
        const int p = kc & 1;
        if (kc < 31) ldgA(kc + 1);
        const uint32_t baseA = sb + OFF_A + p * A_BUF;
        const uint32_t baseB = sb + OFF_B + p * A_BUF;
#pragma unroll
        for (int ks = 0; ks < 4; ks++) {
            uint32_t a[2][4], bg[4][4];
            ldsm_x4(a[0], baseA + (m0 + lr) * SA_STRIDE + ks * 32 + lc * 16);
            ldsm_x4(a[1], baseA + (m0 + 16 + lr) * SA_STRIDE + ks * 32 + lc * 16);
#pragma unroll
            for (int g = 0; g < 4; g++)
                ldsm_x4(bg[g], baseB + (n0 + 16 * g + lr) * SA_STRIDE + ks * 32 + lc * 16);
#pragma unroll
            for (int mi = 0; mi < 2; mi++)
#pragma unroll
                for (int nb = 0; nb < 8; nb++) {
                    uint32_t bb[2] = { bg[nb >> 1][nb & 1], bg[nb >> 1][(nb & 1) + 2] };
                    mma_16816(d[mi][nb], a[mi], bb);
                }
        }
        __syncthreads();        // everyone done reading buffers p
        if (kc < 30) { issueB(kc + 2, p); CP_COMMIT(); }
        if (kc < 31) {
            stsA(p ^ 1);
            if (kc < 30) CP_WAIT(1); else CP_WAIT(0);
            __syncthreads();
        }
    }

    // --- norm: reduce per-row mask counts (8 lanes per row, contiguous tid groups)
#pragma unroll
    for (int s = 0; s < 4; s++) {
        int v = cnt[s];
        v += __shfl_xor_sync(0xffffffffu, v, 1);
        v += __shfl_xor_sync(0xffffffffu, v, 2);
        v += __shfl_xor_sync(0xffffffffu, v, 4);
        if ((tid & 7) == 0) snorm[s * 32 + (tid >> 3)] = v;
    }
    __syncthreads();            // snorm ready; all warps past mma reads of A region

    // --- epilogue 1: scale by 1/norm, fp16, store P tile into A region
#pragma unroll
    for (int mi = 0; mi < 2; mi++) {
        const int r0 = m0 + 16 * mi + gid, r1 = r0 + 8;
        const int c0 = snorm[r0], c1 = snorm[r1];
        const float i0 = (c0 > 0) ? (1.0f / (float)c0) : 1.0f;
        const float i1 = (c1 > 0) ? (1.0f / (float)c1) : 1.0f;
#pragma unroll
        for (int nb = 0; nb < 8; nb++) {
            const int f = n0 + 8 * nb + 2 * tig;
            *(__half2*)(sm + r0 * SW_STRIDE + f * 2) =
                __floats2half2_rn(d[mi][nb][0] * i0, d[mi][nb][1] * i0);
            *(__half2*)(sm + r1 * SW_STRIDE + f * 2) =
                __floats2half2_rn(d[mi][nb][2] * i1, d[mi][nb][3] * i1);
        }
    }
    CP_WAIT(0);                 // W tile resident (done long ago)
    __syncthreads();            // P visible to all warps

    // --- GEMM2: out = relu(P @ W^T + bias), K=128 (8 k-steps)
    float e[2][8][4];
#pragma unroll
    for (int i = 0; i < 2; i++)
#pragma unroll
        for (int j = 0; j < 8; j++)
#pragma unroll
            for (int k = 0; k < 4; k++) e[i][j][k] = 0.0f;

#pragma unroll
    for (int ks = 0; ks < 8; ks++) {
        uint32_t a[2][4], bg[4][4];
        ldsm_x4(a[0], sb + (m0 + lr) * SW_STRIDE + ks * 32 + lc * 16);
        ldsm_x4(a[1], sb + (m0 + 16 + lr) * SW_STRIDE + ks * 32 + lc * 16);
#pragma unroll
        for (int g = 0; g < 4; g++)
            ldsm_x4(bg[g], sb + OFF_W + (n0 + 16 * g + lr) * SW_STRIDE + ks * 32 + lc * 16);
#pragma unroll
        for (int mi = 0; mi < 2; mi++)
#pragma unroll
            for (int nb = 0; nb < 8; nb++) {
                uint32_t bb[2] = { bg[nb >> 1][nb & 1], bg[nb >> 1][(nb & 1) + 2] };
                mma_16816(e[mi][nb], a[mi], bb);
            }
    }

    // --- epilogue 2: bias + relu -> out
    float* outB = out + ((size_t)b * En + e0) * Fn;
#pragma unroll
    for (int mi = 0; mi < 2; mi++) {
        const int r0 = m0 + 16 * mi + gid, r1 = r0 + 8;
#pragma unroll
        for (int nb = 0; nb < 8; nb++) {
            const int f = n0 + 8 * nb + 2 * tig;
            const float bx = sbias[f], by = sbias[f + 1];
            float2 o0, o1;
            o0.x = fmaxf(e[mi][nb][0] + bx, 0.0f);
            o0.y = fmaxf(e[mi][nb][1] + by, 0.0f);
            o1.x = fmaxf(e[mi][nb][2] + bx, 0.0f);
            o1.y = fmaxf(e[mi][nb][3] + by, 0.0f);
            *(float2*)(outB + (size_t)r0 * Fn + f) = o0;
            *(float2*)(outB + (size_t)r1 * Fn + f) = o1;
        }
    }
}

// ---------------------------------------------------------------- launch

extern "C" void kernel_launch(void* const* d_in, const int* in_sizes, int n_in,
                              void* d_out, int out_size) {
    (void)in_sizes; (void)n_in; (void)out_size;
    const float* emb  = (const float*)d_in[0];   // node_embeddings [B,N,F]
    const float* adj  = (const float*)d_in[1];   // adj [B,E,N]
    const float* W    = (const float*)d_in[2];   // [F,F]
    const float* bias = (const float*)d_in[3];   // [F]
    float* out = (float*)d_out;                  // [B,E,F] fp32

    cudaFuncSetAttribute(kmain, cudaFuncAttributeMaxDynamicSharedMemorySize, SMEM_TOT);

    ktr_kernel<<<dim3(Nn / 32, Fn / 32, Bn), dim3(32, 8)>>>(emb);
    kwc_kernel<<<(Fn * Fn) / 256, 256>>>(W);
    kmain<<<Bn * (En / 128), 256, SMEM_TOT>>>(adj, bias, out);
}

// round 15
// speedup vs baseline: 1.2433x; 1.2433x over previous
#include <cuda_runtime.h>
#include <cuda_fp16.h>
#include <cstdint>
#include <cstddef>

#define DEVINL __device__ __forceinline__

static constexpr int Bn = 8, En = 2048, Nn = 2048, Fn = 128;

// Scratch (__device__ globals; allocations are forbidden)
__device__ __half g_embHT[(size_t)Bn * Fn * Nn];   // [b][f][n] fp16, 4 MB
__device__ __half g_WH[Fn * Fn];                   // W fp16 [f_out][f_in]

// ---------------------------------------------------------------- helpers

DEVINL uint32_t smem_u32(const void* p) {
    uint32_t a;
    asm("{ .reg .u64 t; cvta.to.shared.u64 t, %1; cvt.u32.u64 %0, t; }"
        : "=r"(a) : "l"(p));
    return a;
}

DEVINL void ldsm_x4(uint32_t* r, uint32_t addr) {
    asm volatile("ldmatrix.sync.aligned.m8n8.x4.shared.b16 {%0,%1,%2,%3}, [%4];"
                 : "=r"(r[0]), "=r"(r[1]), "=r"(r[2]), "=r"(r[3]) : "r"(addr));
}

DEVINL void mma_16816(float* d, const uint32_t* a, const uint32_t* b) {
    asm volatile(
        "mma.sync.aligned.m16n8k16.row.col.f32.f16.f16.f32 "
        "{%0,%1,%2,%3}, {%4,%5,%6,%7}, {%8,%9}, {%0,%1,%2,%3};"
        : "+f"(d[0]), "+f"(d[1]), "+f"(d[2]), "+f"(d[3])
        : "r"(a[0]), "r"(a[1]), "r"(a[2]), "r"(a[3]), "r"(b[0]), "r"(b[1]));
}

DEVINL void cp_async16(uint32_t dst, const void* src) {
    asm volatile("cp.async.cg.shared.global [%0], [%1], 16;"
                 :: "r"(dst), "l"(src) : "memory");
}
#define CP_COMMIT()  asm volatile("cp.async.commit_group;" ::: "memory")
#define CP_WAIT(N)   asm volatile("cp.async.wait_group %0;" :: "n"(N) : "memory")

// ---------------------------------------------------------------- prelude: transpose+convert emb, convert W
// tiles: 64 (n) x 32 (f). Coalesced 128B loads and 128B fp16 stores.

__global__ void __launch_bounds__(256) kprep(const float* __restrict__ emb,
                                             const float* __restrict__ W) {
    if (blockIdx.x == 32) {
        // W fp32 -> fp16 (32 blocks x 256 threads x 2 elems = 16384)
        const int i = ((blockIdx.z * 4 + blockIdx.y) * 256 + threadIdx.x) * 2;
        const float2 w = *(const float2*)(W + i);
        *(__half2*)(g_WH + i) = __floats2half2_rn(w.x, w.y);
        return;
    }
    __shared__ float t[64][33];
    const int b = blockIdx.z, n0 = blockIdx.x * 64, f0 = blockIdx.y * 32;
    const int tid = threadIdx.x, lane = tid & 31, w = tid >> 5;
#pragma unroll
    for (int r = 0; r < 8; r++) {
        const int i = r * 8 + w;
        t[i][lane] = emb[((size_t)b * Nn + n0 + i) * Fn + f0 + lane];
    }
    __syncthreads();
    const int j = tid >> 3, i0 = (tid & 7) * 8;
    __half hv[8];
#pragma unroll
    for (int q = 0; q < 8; q++) hv[q] = __float2half(t[i0 + q][j]);
    *(uint4*)&g_embHT[((size_t)b * Fn + f0 + j) * Nn + n0 + i0] = *(uint4*)hv;
}

// ---------------------------------------------------------------- fused main kernel
// CTA tile: M=128 hyperedges, N=F=128, K=2048 vertices, BK=64, 3-stage pipeline,
// ONE __syncthreads per K-chunk.
// GEMM1 (mask @ embT, fp16 HMMA, f32 acc) -> /norm -> fp16 P (smem)
// GEMM2 (P @ W^T) -> +bias, relu -> out.

static constexpr int SA_STRIDE = 144;   // 64 halves + 8 pad
static constexpr int SW_STRIDE = 272;   // 128 halves + 8 pad
static constexpr int A_BUF    = 128 * SA_STRIDE;           // 18432
static constexpr int OFF_A    = 0;                         // 3 stages; P reuses
static constexpr int OFF_B    = 3 * A_BUF;                 // 55296, 3 stages
static constexpr int OFF_W    = OFF_B + 3 * A_BUF;         // 110592
static constexpr int OFF_NORM = OFF_W + 128 * SW_STRIDE;   // 145408
static constexpr int OFF_BIAS = OFF_NORM + 512;            // 145920
static constexpr int SMEM_TOT = OFF_BIAS + 512;            // 146432

__global__ void __launch_bounds__(256, 1)
kmain(const float* __restrict__ adj, const float* __restrict__ bias,
      float* __restrict__ out) {
    extern __shared__ char sm[];
    const uint32_t sb = smem_u32(sm);
    const int tid = threadIdx.x;
    const int lane = tid & 31, wid = tid >> 5;
    const int b  = blockIdx.x >> 4;
    const int e0 = (blockIdx.x & 15) << 7;

    float* sbias = (float*)(sm + OFF_BIAS);
    int*   snorm = (int*)(sm + OFF_NORM);
    if (tid < 128) sbias[tid] = bias[tid];

    // --- W tile (32 KB fp16) via cp.async, part of group 0
#pragma unroll
    for (int it = 0; it < 8; it++) {
        const int row = it * 16 + (tid >> 4), c = tid & 15;
        cp_async16(sb + OFF_W + row * SW_STRIDE + c * 16, g_WH + row * Fn + c * 8);
    }

    const __half* embB = g_embHT + (size_t)b * Fn * Nn;
    auto issueB = [&](int kc, int st) {
#pragma unroll
        for (int s = 0; s < 4; s++) {
            const int f = s * 32 + (tid >> 3), c = tid & 7;
            cp_async16(sb + OFF_B + st * A_BUF + f * SA_STRIDE + c * 16,
                       embB + (size_t)f * Nn + kc * 64 + c * 8);
        }
    };

    const float* adjB = adj + ((size_t)b * En + e0) * Nn;
    float4 av[4][2];
    auto ldgA = [&](int kc) {
#pragma unroll
        for (int s = 0; s < 4; s++) {
            const float* p = adjB + (size_t)(s * 32 + (tid >> 3)) * Nn
                           + kc * 64 + (tid & 7) * 8;
            av[s][0] = *(const float4*)p;
            av[s][1] = *(const float4*)(p + 4);
        }
    };

    int cnt[4] = {0, 0, 0, 0};
    auto stsA = [&](int st) {
#pragma unroll
        for (int s = 0; s < 4; s++) {
            const int row = s * 32 + (tid >> 3);
            uint32_t m0 = (av[s][0].x == -1.0f) ? 0x3C00u : 0u;
            uint32_t m1 = (av[s][0].y == -1.0f) ? 0x3C00u : 0u;
            uint32_t m2 = (av[s][0].z == -1.0f) ? 0x3C00u : 0u;
            uint32_t m3 = (av[s][0].w == -1.0f) ? 0x3C00u : 0u;
            uint32_t m4 = (av[s][1].x == -1.0f) ? 0x3C00u : 0u;
            uint32_t m5 = (av[s][1].y == -1.0f) ? 0x3C00u : 0u;
            uint32_t m6 = (av[s][1].z == -1.0f) ? 0x3C00u : 0u;
            uint32_t m7 = (av[s][1].w == -1.0f) ? 0x3C00u : 0u;
            cnt[s] += (m0 ? 1 : 0) + (m1 ? 1 : 0) + (m2 ? 1 : 0) + (m3 ? 1 : 0)
                    + (m4 ? 1 : 0) + (m5 ? 1 : 0) + (m6 ? 1 : 0) + (m7 ? 1 : 0);
            uint4 q;
            q.x = m0 | (m1 << 16); q.y = m2 | (m3 << 16);
            q.z = m4 | (m5 << 16); q.w = m6 | (m7 << 16);
            *(uint4*)(sm + OFF_A + st * A_BUF + row * SA_STRIDE + (tid & 7) * 16) = q;
        }
    };

    // --- prologue: stages 0,1 filled; av holds chunk 2
    issueB(0, 0); CP_COMMIT();          // G0 = W + B0
    ldgA(0);
    issueB(1, 1); CP_COMMIT();          // G1 = B1
    stsA(0);
    ldgA(1);
    stsA(1);
    ldgA(2);
    CP_WAIT(1);                          // G0 (W + B0) complete
    __syncthreads();

    // --- warp tiling: 4 (M) x 2 (N); warp tile 32m x 64n
    const int mw = wid & 3, nw = wid >> 2;
    const int m0 = mw * 32, n0 = nw * 64;
    const int lr = lane & 15, lc = lane >> 4;
    const int gid = lane >> 2, tig = lane & 3;

    float d[2][8][4];
#pragma unroll
    for (int i = 0; i < 2; i++)
#pragma unroll
        for (int j = 0; j < 8; j++)
#pragma unroll
            for (int k = 0; k < 4; k++) d[i][j][k] = 0.0f;

    for (int kc = 0; kc < 32; kc++) {
        const int s = kc % 3;
        const uint32_t baseA = sb + OFF_A + s * A_BUF;
        const uint32_t baseB = sb + OFF_B + s * A_BUF;
#pragma unroll
        for (int ks = 0; ks < 4; ks++) {
            uint32_t a[2][4], bg[4][4];
            ldsm_x4(a[0], baseA + (m0 + lr) * SA_STRIDE + ks * 32 + lc * 16);
            ldsm_x4(a[1], baseA + (m0 + 16 + lr) * SA_STRIDE + ks * 32 + lc * 16);
#pragma unroll
            for (int g = 0; g < 4; g++)
                ldsm_x4(bg[g], baseB + (n0 + 16 * g + lr) * SA_STRIDE + ks * 32 + lc * 16);
#pragma unroll
            for (int mi = 0; mi < 2; mi++)
#pragma unroll
                for (int nb = 0; nb < 8; nb++) {
                    uint32_t bb[2] = { bg[nb >> 1][nb & 1], bg[nb >> 1][(nb & 1) + 2] };
                    mma_16816(d[mi][nb], a[mi], bb);
                }
        }
        // producers: fill stage (kc+2)%3 == (kc-1)%3 (last read before bar(kc-1))
        if (kc < 30) {
            const int st = (kc + 2) % 3;
            stsA(st);                    // av = chunk kc+2
            if (kc < 29) ldgA(kc + 3);
            issueB(kc + 2, st); CP_COMMIT();
            CP_WAIT(1);                  // B(kc+1) complete; only B(kc+2) in flight
        } else {
            CP_WAIT(0);
        }
        __syncthreads();
    }

    // --- norm: reduce per-row mask counts (8 lanes per row)
#pragma unroll
    for (int s = 0; s < 4; s++) {
        int v = cnt[s];
        v += __shfl_xor_sync(0xffffffffu, v, 1);
        v += __shfl_xor_sync(0xffffffffu, v, 2);
        v += __shfl_xor_sync(0xffffffffu, v, 4);
        if ((tid & 7) == 0) snorm[s * 32 + (tid >> 3)] = v;
    }
    __syncthreads();

    // --- epilogue 1: scale by 1/norm, fp16, store P tile into A region
#pragma unroll
    for (int mi = 0; mi < 2; mi++) {
        const int r0 = m0 + 16 * mi + gid, r1 = r0 + 8;
        const int c0 = snorm[r0], c1 = snorm[r1];
        const float i0 = (c0 > 0) ? (1.0f / (float)c0) : 1.0f;
        const float i1 = (c1 > 0) ? (1.0f / (float)c1) : 1.0f;
#pragma unroll
        for (int nb = 0; nb < 8; nb++) {
            const int f = n0 + 8 * nb + 2 * tig;
            *(__half2*)(sm + r0 * SW_STRIDE + f * 2) =
                __floats2half2_rn(d[mi][nb][0] * i0, d[mi][nb][1] * i0);
            *(__half2*)(sm + r1 * SW_STRIDE + f * 2) =
                __floats2half2_rn(d[mi][nb][2] * i1, d[mi][nb][3] * i1);
        }
    }
    __syncthreads();            // P visible to all warps (W resident long ago)

    // --- GEMM2: out = relu(P @ W^T + bias), K=128 (8 k-steps)
    float e[2][8][4];
#pragma unroll
    for (int i = 0; i < 2; i++)
#pragma unroll
        for (int j = 0; j < 8; j++)
#pragma unroll
            for (int k = 0; k < 4; k++) e[i][j][k] = 0.0f;

#pragma unroll
    for (int ks = 0; ks < 8; ks++) {
        uint32_t a[2][4], bg[4][4];
        ldsm_x4(a[0], sb + (m0 + lr) * SW_STRIDE + ks * 32 + lc * 16);
        ldsm_x4(a[1], sb + (m0 + 16 + lr) * SW_STRIDE + ks * 32 + lc * 16);
#pragma unroll
        for (int g = 0; g < 4; g++)
            ldsm_x4(bg[g], sb + OFF_W + (n0 + 16 * g + lr) * SW_STRIDE + ks * 32 + lc * 16);
#pragma unroll
        for (int mi = 0; mi < 2; mi++)
#pragma unroll
            for (int nb = 0; nb < 8; nb++) {
                uint32_t bb[2] = { bg[nb >> 1][nb & 1], bg[nb >> 1][(nb & 1) + 2] };
                mma_16816(e[mi][nb], a[mi], bb);
            }
    }

    // --- epilogue 2: bias + relu -> out
    float* outB = out + ((size_t)b * En + e0) * Fn;
#pragma unroll
    for (int mi = 0; mi < 2; mi++) {
        const int r0 = m0 + 16 * mi + gid, r1 = r0 + 8;
#pragma unroll
        for (int nb = 0; nb < 8; nb++) {
            const int f = n0 + 8 * nb + 2 * tig;
            const float bx = sbias[f], by = sbias[f + 1];
            float2 o0, o1;
            o0.x = fmaxf(e[mi][nb][0] + bx, 0.0f);
            o0.y = fmaxf(e[mi][nb][1] + by, 0.0f);
            o1.x = fmaxf(e[mi][nb][2] + bx, 0.0f);
            o1.y = fmaxf(e[mi][nb][3] + by, 0.0f);
            *(float2*)(outB + (size_t)r0 * Fn + f) = o0;
            *(float2*)(outB + (size_t)r1 * Fn + f) = o1;
        }
    }
}

// ---------------------------------------------------------------- launch

extern "C" void kernel_launch(void* const* d_in, const int* in_sizes, int n_in,
                              void* d_out, int out_size) {
    (void)in_sizes; (void)n_in; (void)out_size;
    const float* emb  = (const float*)d_in[0];   // node_embeddings [B,N,F]
    const float* adj  = (const float*)d_in[1];   // adj [B,E,N]
    const float* W    = (const float*)d_in[2];   // [F,F]
    const float* bias = (const float*)d_in[3];   // [F]
    float* out = (float*)d_out;                  // [B,E,F] fp32

    cudaFuncSetAttribute(kmain, cudaFuncAttributeMaxDynamicSharedMemorySize, SMEM_TOT);

    kprep<<<dim3(33, 4, Bn), 256>>>(emb, W);
    kmain<<<Bn * (En / 128), 256, SMEM_TOT>>>(adj, bias, out);
}